// round 1
// baseline (speedup 1.0000x reference)
#include <cuda_runtime.h>

// YOLOv1 loss, GB300 (sm_103a).
// pred/target: [16384, 7, 7, 30] fp32. Output: scalar fp32.
// Strategy: HBM-streaming reduction. Coalesced float4 tile loads -> smem ->
// per-cell math -> hierarchical reduction -> atomicAdd(out, blockSum/N).

#define N_BATCH   16384
#define N_CELLS   (N_BATCH * 49)      // 802816
#define TILE      128                  // cells per block
#define THREADS   128
#define N_TILES   (N_CELLS / TILE)     // 6272, exact
#define FLOATS_PER_TILE (TILE * 30)    // 3840
#define VEC4_PER_TILE   (FLOATS_PER_TILE / 4) // 960

__global__ void zero_out_kernel(float* out) { out[0] = 0.0f; }

__global__ __launch_bounds__(THREADS)
void yolo_loss_kernel(const float* __restrict__ pred,
                      const float* __restrict__ targ,
                      float* __restrict__ out)
{
    __shared__ float sp[FLOATS_PER_TILE];
    __shared__ float st[FLOATS_PER_TILE];

    const long base = (long)blockIdx.x * FLOATS_PER_TILE;

    // Coalesced stage-in: 960 float4 per tensor, lanes consecutive.
    const float4* __restrict__ gp4 = (const float4*)(pred + base);
    const float4* __restrict__ gt4 = (const float4*)(targ + base);
    float4* sp4 = (float4*)sp;
    float4* st4 = (float4*)st;
    #pragma unroll
    for (int i = threadIdx.x; i < VEC4_PER_TILE; i += THREADS) {
        sp4[i] = gp4[i];
        st4[i] = gt4[i];
    }
    __syncthreads();

    const float* p = sp + threadIdx.x * 30;
    const float* t = st + threadIdx.x * 30;

    float loss;
    if (!(t[4] > 0.0f)) {
        // no-object cell: 0.5 * ((p4-t4)^2 + (p9-t9)^2)
        float d4 = p[4] - t[4];
        float d9 = p[9] - t[9];
        loss = 0.5f * (d4 * d4 + d9 * d9);
    } else {
        // class loss: sum over channels 10..29
        float cls = 0.0f;
        #pragma unroll
        for (int j = 10; j < 30; j++) {
            float d = p[j] - t[j];
            cls += d * d;
        }

        // target box 0 corners (replicate reference arithmetic exactly)
        float tltx = t[0] - 0.5f * t[2];
        float tlty = t[1] - 0.5f * t[3];
        float trbx = t[0] + 0.5f * t[2];
        float trby = t[1] + 0.5f * t[3];
        float area2 = (trbx - tltx) * (trby - tlty);

        float iou0, iou1;
        #pragma unroll
        for (int b = 0; b < 2; b++) {
            const float* q = p + b * 5;
            float pltx = q[0] - 0.5f * q[2];
            float plty = q[1] - 0.5f * q[3];
            float prbx = q[0] + 0.5f * q[2];
            float prby = q[1] + 0.5f * q[3];
            float ltx = fmaxf(pltx, tltx);
            float lty = fmaxf(plty, tlty);
            float rbx = fminf(prbx, trbx);
            float rby = fminf(prby, trby);
            // reference quirk: "intersection" indicator is (rb - lt < 0)
            float inter = (((rbx - ltx) < 0.0f) ? 1.0f : 0.0f) *
                          (((rby - lty) < 0.0f) ? 1.0f : 0.0f);
            float area1 = (prbx - pltx) * (prby - plty);
            float iou = inter / (area1 + area2 - inter);
            if (b == 0) iou0 = iou; else iou1 = iou;
        }
        // argmax, tie -> box 0
        int idx = (iou1 > iou0) ? 1 : 0;
        const float* rp = p + idx * 5;
        const float* rt = t + idx * 5;

        float dc = rp[4] - rt[4];                    // contain loss
        float dx = rp[0] - rt[0];
        float dy = rp[1] - rt[1];
        float dw = sqrtf(rp[2]) - sqrtf(rt[2]);      // inputs in [0,1): sqrt safe
        float dh = sqrtf(rp[3]) - sqrtf(rt[3]);

        loss = cls + dc * dc + 5.0f * (dx * dx + dy * dy + dw * dw + dh * dh);
    }

    // Scale by 1/N here so the final atomic accumulates the finished value.
    float v = loss * (1.0f / (float)N_BATCH);

    // warp reduction
    #pragma unroll
    for (int o = 16; o > 0; o >>= 1)
        v += __shfl_down_sync(0xFFFFFFFFu, v, o);

    __shared__ float wsum[THREADS / 32];
    if ((threadIdx.x & 31) == 0) wsum[threadIdx.x >> 5] = v;
    __syncthreads();

    if (threadIdx.x == 0) {
        float bs = 0.0f;
        #pragma unroll
        for (int w = 0; w < THREADS / 32; w++) bs += wsum[w];
        atomicAdd(out, bs);
    }
}

extern "C" void kernel_launch(void* const* d_in, const int* in_sizes, int n_in,
                              void* d_out, int out_size)
{
    const float* pred = (const float*)d_in[0];
    const float* targ = (const float*)d_in[1];
    float* out = (float*)d_out;

    zero_out_kernel<<<1, 1>>>(out);
    yolo_loss_kernel<<<N_TILES, THREADS>>>(pred, targ, out);
}

// round 2
// speedup vs baseline: 1.1138x; 1.1138x over previous
#include <cuda_runtime.h>
#include <cstdint>

// YOLOv1 loss, GB300 (sm_103a).
// pred/target: [16384, 7, 7, 30] fp32 (96.3 MB each). Output: scalar fp32.
// Strategy: persistent blocks, cp.async (LDGSTS) double-buffered smem tiles,
// branchless per-cell math, register accumulation across tiles, one atomicAdd
// per block. Pure HBM-streaming reduction; floor ~24us at 8TB/s.

#define N_BATCH   16384
#define N_CELLS   (N_BATCH * 49)          // 802816
#define TILE      128                      // cells per tile
#define THREADS   128
#define N_TILES   (N_CELLS / TILE)         // 6272, exact
#define FLOATS_PER_TENSOR_TILE (TILE * 30) // 3840 floats = 15360 B
#define VEC4_PER_TENSOR_TILE   (FLOATS_PER_TENSOR_TILE / 4) // 960
#define BUF_FLOATS (2 * FLOATS_PER_TENSOR_TILE)             // p + t = 7680
#define SMEM_BYTES (2 * BUF_FLOATS * 4)                     // 61440 (double buffer)
#define GRID      444                      // 148 SMs * 3 blocks/SM

__global__ void zero_out_kernel(float* out) { out[0] = 0.0f; }

__device__ __forceinline__ void cp_async16(void* smem_dst, const void* gmem_src) {
    uint32_t sa = (uint32_t)__cvta_generic_to_shared(smem_dst);
    asm volatile("cp.async.cg.shared.global [%0], [%1], 16;\n"
                 :: "r"(sa), "l"(gmem_src));
}
__device__ __forceinline__ void cp_commit() {
    asm volatile("cp.async.commit_group;\n" ::: "memory");
}
template <int N>
__device__ __forceinline__ void cp_wait() {
    asm volatile("cp.async.wait_group %0;\n" :: "n"(N) : "memory");
}

// Issue the cp.async loads for one tile into buffer `sbuf`.
// sbuf layout: [0,3840) pred floats, [3840,7680) target floats.
__device__ __forceinline__ void prefetch_tile(const float* __restrict__ pred,
                                              const float* __restrict__ targ,
                                              float* sbuf, int tile, int tid)
{
    const float4* gp4 = (const float4*)(pred + (long)tile * FLOATS_PER_TENSOR_TILE);
    const float4* gt4 = (const float4*)(targ + (long)tile * FLOATS_PER_TENSOR_TILE);
    float4* sp4 = (float4*)sbuf;
    float4* st4 = (float4*)(sbuf + FLOATS_PER_TENSOR_TILE);
    // 960 float4 per tensor, 128 threads: 7 full rounds + half round.
    #pragma unroll
    for (int k = 0; k < 7; k++) {
        int i = tid + k * THREADS;
        cp_async16(&sp4[i], &gp4[i]);
        cp_async16(&st4[i], &gt4[i]);
    }
    if (tid < 64) {
        int i = tid + 7 * THREADS;
        cp_async16(&sp4[i], &gp4[i]);
        cp_async16(&st4[i], &gt4[i]);
    }
}

// Per-cell loss (branchless; replicates reference arithmetic exactly).
__device__ __forceinline__ float cell_loss(const float* __restrict__ p,
                                           const float* __restrict__ t)
{
    // no-object term
    float d4 = p[4] - t[4];
    float d9 = p[9] - t[9];
    float noo_l = 0.5f * (d4 * d4 + d9 * d9);

    // class loss (ch 10..29)
    float cls = 0.0f;
    #pragma unroll
    for (int j = 10; j < 30; j++) {
        float d = p[j] - t[j];
        cls = fmaf(d, d, cls);
    }

    // target box 0 corners
    float tltx = t[0] - 0.5f * t[2];
    float tlty = t[1] - 0.5f * t[3];
    float trbx = t[0] + 0.5f * t[2];
    float trby = t[1] + 0.5f * t[3];
    float area2 = (trbx - tltx) * (trby - tlty);

    float iou0 = 0.0f, iou1 = 0.0f;
    #pragma unroll
    for (int b = 0; b < 2; b++) {
        const float* q = p + b * 5;
        float pltx = q[0] - 0.5f * q[2];
        float plty = q[1] - 0.5f * q[3];
        float prbx = q[0] + 0.5f * q[2];
        float prby = q[1] + 0.5f * q[3];
        float ltx = fmaxf(pltx, tltx);
        float lty = fmaxf(plty, tlty);
        float rbx = fminf(prbx, trbx);
        float rby = fminf(prby, trby);
        // reference quirk: indicator is (rb - lt < 0)
        float inter = (((rbx - ltx) < 0.0f) ? 1.0f : 0.0f) *
                      (((rby - lty) < 0.0f) ? 1.0f : 0.0f);
        float area1 = (prbx - pltx) * (prby - plty);
        float iou = inter / (area1 + area2 - inter);
        if (b == 0) iou0 = iou; else iou1 = iou;
    }
    int idx = (iou1 > iou0) ? 1 : 0;   // argmax, tie -> box 0
    const float* rp = p + idx * 5;
    const float* rt = t + idx * 5;

    float dc = rp[4] - rt[4];
    float dx = rp[0] - rt[0];
    float dy = rp[1] - rt[1];
    float dw = sqrtf(rp[2]) - sqrtf(rt[2]);   // inputs in [0,1): sqrt safe
    float dh = sqrtf(rp[3]) - sqrtf(rt[3]);

    float obj_l = cls + dc * dc + 5.0f * (dx * dx + dy * dy + dw * dw + dh * dh);

    return (t[4] > 0.0f) ? obj_l : noo_l;
}

__global__ __launch_bounds__(THREADS)
void yolo_loss_kernel(const float* __restrict__ pred,
                      const float* __restrict__ targ,
                      float* __restrict__ out)
{
    extern __shared__ float smem[];   // 2 buffers of BUF_FLOATS each
    const int tid = threadIdx.x;

    float acc = 0.0f;
    int buf = 0;

    int tile = blockIdx.x;
    if (tile < N_TILES) {
        prefetch_tile(pred, targ, smem, tile, tid);
        cp_commit();
    }

    for (; tile < N_TILES; tile += GRID) {
        int next = tile + GRID;
        if (next < N_TILES) {
            prefetch_tile(pred, targ, smem + (buf ^ 1) * BUF_FLOATS, next, tid);
            cp_commit();
            cp_wait<1>();      // current tile's group done; next still in flight
        } else {
            cp_wait<0>();
        }
        __syncthreads();

        const float* sbuf = smem + buf * BUF_FLOATS;
        acc += cell_loss(sbuf + tid * 30,
                         sbuf + FLOATS_PER_TENSOR_TILE + tid * 30);

        __syncthreads();       // all reads of `buf` done before it is refilled
        buf ^= 1;
    }

    // block reduction
    acc *= (1.0f / (float)N_BATCH);
    #pragma unroll
    for (int o = 16; o > 0; o >>= 1)
        acc += __shfl_down_sync(0xFFFFFFFFu, acc, o);

    __shared__ float wsum[THREADS / 32];
    if ((tid & 31) == 0) wsum[tid >> 5] = acc;
    __syncthreads();
    if (tid == 0) {
        float bs = 0.0f;
        #pragma unroll
        for (int w = 0; w < THREADS / 32; w++) bs += wsum[w];
        atomicAdd(out, bs);
    }
}

extern "C" void kernel_launch(void* const* d_in, const int* in_sizes, int n_in,
                              void* d_out, int out_size)
{
    const float* pred = (const float*)d_in[0];
    const float* targ = (const float*)d_in[1];
    float* out = (float*)d_out;

    cudaFuncSetAttribute(yolo_loss_kernel,
                         cudaFuncAttributeMaxDynamicSharedMemorySize, SMEM_BYTES);

    zero_out_kernel<<<1, 1>>>(out);
    yolo_loss_kernel<<<GRID, THREADS, SMEM_BYTES>>>(pred, targ, out);
}